// round 10
// baseline (speedup 1.0000x reference)
#include <cuda_runtime.h>

#define R_REGIONS 10000
#define KBINS 32
#define NPTS 2000000
#define VEC 4
#define GCELLS 64

// Scratch (allocation-free rule: __device__ globals)
__device__ float  g_edges[R_REGIONS * KBINS];        // bin left edges (rare fallback)
__device__ float4 g_params[R_REGIONS * KBINS * 2];   // packed per-bin coefficients
__device__ float4 g_grid[R_REGIONS * GCELLS * 2];    // 32B per grid cell (20.5 MB)

// ---------------------------------------------------------------------------
// Fused build kernel: one warp per region (8 regions / 256-thread block).
//  Phase A (registers): softmax(widths), exp+trapezoid-normalize(heights),
//    dual inclusive scan -> per-bin {loc_l, inv_w, A, B, cdf_l, dh, h_l}.
//  Phase B (shared): each warp builds its region's 64 grid-cell records.
//  Record (2x float4 = 32B):
//    single-bin cell: {flag=-1, loc_l, inv_w, A} {B, cdf_l, dh, h_l}
//    multi-bin cell : {b0>=0,   e1, e2, e3}      {e4, e5, e6, e7} (2.0f pad)
// ---------------------------------------------------------------------------
__global__ void __launch_bounds__(256)
build_kernel(const float* __restrict__ uw, const float* __restrict__ uh) {
    __shared__ float s_edge[8][KBINS];
    __shared__ float s_par[8][KBINS][9];   // stride 9: bank-conflict-free reads

    const unsigned FULL = 0xffffffffu;
    int wib  = threadIdx.x >> 5;
    int lane = threadIdx.x & 31;
    int r = blockIdx.x * 8 + wib;
    if (r >= R_REGIONS) return;

    // ---- Phase A ----
    float w_raw = uw[r * KBINS + lane];
    float m = w_raw;
    #pragma unroll
    for (int o = 16; o; o >>= 1) m = fmaxf(m, __shfl_xor_sync(FULL, m, o));
    float e = expf(w_raw - m);
    float s = e;
    #pragma unroll
    for (int o = 16; o; o >>= 1) s += __shfl_xor_sync(FULL, s, o);
    float w = e / s;

    float hk  = expf(uh[r * (KBINS + 1) + lane]);
    float hk1 = __shfl_down_sync(FULL, hk, 1);
    if (lane == 31) hk1 = expf(uh[r * (KBINS + 1) + KBINS]);
    float seg_raw = 0.5f * (hk + hk1) * w;
    float area = seg_raw;
    #pragma unroll
    for (int o = 16; o; o >>= 1) area += __shfl_xor_sync(FULL, area, o);
    float inv_area = 1.0f / area;
    float h_l = hk * inv_area;
    float h_r = hk1 * inv_area;
    float seg = seg_raw * inv_area;

    float cdf_r = seg;
    float loc_r = w;
    #pragma unroll
    for (int o = 1; o < 32; o <<= 1) {
        float t1 = __shfl_up_sync(FULL, cdf_r, o);
        float t2 = __shfl_up_sync(FULL, loc_r, o);
        if (lane >= o) { cdf_r += t1; loc_r += t2; }
    }
    float cdf_l = cdf_r - seg;
    float loc_l = loc_r - w;
    if (lane == 0) { cdf_l = 0.0f; loc_l = 0.0f; }

    float inv_w = 1.0f / w;
    float dh    = h_r - h_l;
    float A     = 0.5f * dh * w;
    float B     = h_l * w;

    // Global tables (multi-cell path + rare fallback in eval)
    g_edges[r * KBINS + lane] = loc_l;
    g_params[(r * KBINS + lane) * 2 + 0] = make_float4(loc_l, inv_w, A, B);
    g_params[(r * KBINS + lane) * 2 + 1] = make_float4(cdf_l, dh, h_l, 0.0f);

    // Stage to shared for Phase B
    s_edge[wib][lane] = loc_l;
    s_par[wib][lane][0] = loc_l;  s_par[wib][lane][1] = inv_w;
    s_par[wib][lane][2] = A;      s_par[wib][lane][3] = B;
    s_par[wib][lane][4] = cdf_l;  s_par[wib][lane][5] = dh;
    s_par[wib][lane][6] = h_l;
    __syncwarp();

    // ---- Phase B: 2 grid cells per lane ----
    const float* ev = s_edge[wib];
    #pragma unroll
    for (int half = 0; half < 2; half++) {
        int g = lane + half * 32;
        float xg = (float)g * (1.0f / GCELLS);
        float xn = (float)(g + 1) * (1.0f / GCELLS);

        int b0 = (xg >= ev[16]) ? 16 : 0;
        b0 += (xg >= ev[b0 + 8]) ? 8 : 0;
        b0 += (xg >= ev[b0 + 4]) ? 4 : 0;
        b0 += (xg >= ev[b0 + 2]) ? 2 : 0;
        b0 += (xg >= ev[b0 + 1]) ? 1 : 0;

        bool single = (b0 >= KBINS - 1) || (ev[b0 + 1] >= xn);

        float4 ra, rb;
        if (single) {
            const float* p = s_par[wib][b0];
            ra = make_float4(__int_as_float(-1), p[0], p[1], p[2]);
            rb = make_float4(p[3], p[4], p[5], p[6]);
        } else {
            float ee[7];
            #pragma unroll
            for (int j = 0; j < 7; j++) {
                int idx = b0 + 1 + j;
                ee[j] = (idx < KBINS) ? ev[idx] : 2.0f;
            }
            ra = make_float4(__int_as_float(b0), ee[0], ee[1], ee[2]);
            rb = make_float4(ee[3], ee[4], ee[5], ee[6]);
        }
        g_grid[(r * GCELLS + g) * 2 + 0] = ra;
        g_grid[(r * GCELLS + g) * 2 + 1] = rb;
    }
}

// ---------------------------------------------------------------------------
// Eval: FOUR points per thread, phase-structured for MLP:
//   P1: 4 grid-record loads (batched)
//   P2: bin resolution for all 4 (incl. ~never-taken saturated walk)
//   P3: 4 predicated params loads back-to-back (batched, MLP=4)
//   P4: selects + math + vector stores
// Cell index floor(x*64) is EXACT in fp32 (power-of-two multiply) -> no guard.
// ---------------------------------------------------------------------------
__global__ void __launch_bounds__(256)
eval_points_kernel(const float4* __restrict__ x4,
                   const int4* __restrict__ ridx4,
                   float* __restrict__ out) {
    int t = blockIdx.x * blockDim.x + threadIdx.x;
    if (t >= NPTS / VEC) return;

    float4 xv = x4[t];
    int4   rv = ridx4[t];
    float xs[VEC] = {xv.x, xv.y, xv.z, xv.w};
    int   rs[VEC] = {rv.x, rv.y, rv.z, rv.w};

    // P1: grid-record loads
    float4 ra[VEC], rb[VEC];
    #pragma unroll
    for (int k = 0; k < VEC; k++) {
        int g = min((int)(xs[k] * (float)GCELLS), GCELLS - 1);  // exact
        const float4* rec = g_grid + (rs[k] * GCELLS + g) * 2;
        ra[k] = __ldg(rec + 0);
        rb[k] = __ldg(rec + 1);
    }

    // P2: bin resolution (branch-free except the ~never saturated walk)
    bool multi[VEC];
    int  b[VEC];
    #pragma unroll
    for (int k = 0; k < VEC; k++) {
        float x = xs[k];
        multi[k] = (__float_as_int(ra[k].x) >= 0);
        int cnt = (x >= ra[k].y) + (x >= ra[k].z) + (x >= ra[k].w)
                + (x >= rb[k].x) + (x >= rb[k].y) + (x >= rb[k].z)
                + (x >= rb[k].w);
        b[k] = __float_as_int(ra[k].x) + cnt;
        if (multi[k] && cnt == 7) {  // saturated cell: exact fallback (~never)
            const float* e = g_edges + rs[k] * KBINS;
            while (b[k] < KBINS - 1 && x >= __ldg(e + b[k] + 1)) b[k]++;
        }
    }

    // P3: batched predicated params loads (no branches between -> MLP=4)
    float4 p0[VEC], p1[VEC];
    #pragma unroll
    for (int k = 0; k < VEC; k++) { p0[k] = ra[k]; p1[k] = rb[k]; }
    #pragma unroll
    for (int k = 0; k < VEC; k++) {
        if (multi[k]) {
            const float4* p = g_params + (rs[k] * KBINS + b[k]) * 2;
            p0[k] = __ldg(p + 0);   // {loc_l, inv_w, A, B}
            p1[k] = __ldg(p + 1);   // {cdf_l, dh, h_l, _}
        }
    }

    // P4: unified epilogue (single-bin embeds params shifted by one slot)
    float outv[VEC], lad[VEC];
    #pragma unroll
    for (int k = 0; k < VEC; k++) {
        bool mt = multi[k];
        float loc_l = mt ? p0[k].x : ra[k].y;
        float inv_w = mt ? p0[k].y : ra[k].z;
        float A     = mt ? p0[k].z : ra[k].w;
        float B     = mt ? p0[k].w : rb[k].x;
        float cdf_l = mt ? p1[k].x : rb[k].y;
        float dh    = mt ? p1[k].y : rb[k].z;
        float h_l   = mt ? p1[k].z : rb[k].w;

        float alpha = (xs[k] - loc_l) * inv_w;
        outv[k] = fmaf(fmaf(A, alpha, B), alpha, cdf_l);
        lad[k]  = __logf(fmaf(dh, alpha, h_l));
    }

    __stcs((float4*)(out) + t, make_float4(outv[0], outv[1], outv[2], outv[3]));
    __stcs((float4*)(out + NPTS) + t, make_float4(lad[0], lad[1], lad[2], lad[3]));
}

extern "C" void kernel_launch(void* const* d_in, const int* in_sizes, int n_in,
                              void* d_out, int out_size) {
    const float* x    = (const float*)d_in[0];
    const int*   ridx = (const int*)d_in[1];
    // Defensive binding: uw has R*K = 320000 elems, uh has R*(K+1) = 330000.
    const float* uw   = (const float*)d_in[2];
    const float* uh   = (const float*)d_in[3];
    if (n_in >= 4 && in_sizes[2] == R_REGIONS * (KBINS + 1)
                  && in_sizes[3] == R_REGIONS * KBINS) {
        const float* tmp = uw; uw = uh; uh = tmp;
    }
    float* out = (float*)d_out;

    int blocks1 = (R_REGIONS + 7) / 8;      // 8 warps (regions) per block
    build_kernel<<<blocks1, 256>>>(uw, uh);

    int threads2 = NPTS / VEC;
    int blocks2 = (threads2 + 255) / 256;
    eval_points_kernel<<<blocks2, 256>>>((const float4*)x, (const int4*)ridx, out);
}

// round 12
// speedup vs baseline: 1.1240x; 1.1240x over previous
#include <cuda_runtime.h>

#define R_REGIONS 10000
#define KBINS 32
#define NPTS 2000000
#define VEC 4
#define GCELLS 64

// Scratch (allocation-free rule: __device__ globals). 32B alignment for v8 ld/st.
__device__ __align__(32) float  g_edges[R_REGIONS * KBINS];
__device__ __align__(32) float4 g_params[R_REGIONS * KBINS * 2];
__device__ __align__(32) float4 g_grid[R_REGIONS * GCELLS * 2];

// 256-bit global load/store (sm_100+): one L1tex wavefront instead of two.
__device__ __forceinline__ void ldg256(const float4* p, float4& a, float4& b) {
    asm volatile("ld.global.nc.v8.f32 {%0,%1,%2,%3,%4,%5,%6,%7}, [%8];"
        : "=f"(a.x), "=f"(a.y), "=f"(a.z), "=f"(a.w),
          "=f"(b.x), "=f"(b.y), "=f"(b.z), "=f"(b.w)
        : "l"(p));
}
__device__ __forceinline__ void stg256(float4* p, float4 a, float4 b) {
    asm volatile("st.global.v8.f32 [%0], {%1,%2,%3,%4,%5,%6,%7,%8};"
        :: "l"(p), "f"(a.x), "f"(a.y), "f"(a.z), "f"(a.w),
           "f"(b.x), "f"(b.y), "f"(b.z), "f"(b.w) : "memory");
}

// ---------------------------------------------------------------------------
// Fused build kernel: one warp per region (8 regions / 256-thread block).
// ---------------------------------------------------------------------------
__global__ void __launch_bounds__(256)
build_kernel(const float* __restrict__ uw, const float* __restrict__ uh) {
    __shared__ float s_edge[8][KBINS];
    __shared__ float s_par[8][KBINS][9];   // stride 9: bank-conflict-free reads

    const unsigned FULL = 0xffffffffu;
    int wib  = threadIdx.x >> 5;
    int lane = threadIdx.x & 31;
    int r = blockIdx.x * 8 + wib;
    if (r >= R_REGIONS) return;

    // ---- Phase A: spline parameters ----
    float w_raw = uw[r * KBINS + lane];
    float m = w_raw;
    #pragma unroll
    for (int o = 16; o; o >>= 1) m = fmaxf(m, __shfl_xor_sync(FULL, m, o));
    float e = expf(w_raw - m);
    float s = e;
    #pragma unroll
    for (int o = 16; o; o >>= 1) s += __shfl_xor_sync(FULL, s, o);
    float w = e / s;

    float hk  = expf(uh[r * (KBINS + 1) + lane]);
    float hk1 = __shfl_down_sync(FULL, hk, 1);
    if (lane == 31) hk1 = expf(uh[r * (KBINS + 1) + KBINS]);
    float seg_raw = 0.5f * (hk + hk1) * w;
    float area = seg_raw;
    #pragma unroll
    for (int o = 16; o; o >>= 1) area += __shfl_xor_sync(FULL, area, o);
    float inv_area = 1.0f / area;
    float h_l = hk * inv_area;
    float h_r = hk1 * inv_area;
    float seg = seg_raw * inv_area;

    float cdf_r = seg;
    float loc_r = w;
    #pragma unroll
    for (int o = 1; o < 32; o <<= 1) {
        float t1 = __shfl_up_sync(FULL, cdf_r, o);
        float t2 = __shfl_up_sync(FULL, loc_r, o);
        if (lane >= o) { cdf_r += t1; loc_r += t2; }
    }
    float cdf_l = cdf_r - seg;
    float loc_l = loc_r - w;
    if (lane == 0) { cdf_l = 0.0f; loc_l = 0.0f; }

    float inv_w = 1.0f / w;
    float dh    = h_r - h_l;
    float A     = 0.5f * dh * w;
    float B     = h_l * w;

    g_edges[r * KBINS + lane] = loc_l;
    stg256(&g_params[(r * KBINS + lane) * 2],
           make_float4(loc_l, inv_w, A, B),
           make_float4(cdf_l, dh, h_l, 0.0f));

    s_edge[wib][lane] = loc_l;
    s_par[wib][lane][0] = loc_l;  s_par[wib][lane][1] = inv_w;
    s_par[wib][lane][2] = A;      s_par[wib][lane][3] = B;
    s_par[wib][lane][4] = cdf_l;  s_par[wib][lane][5] = dh;
    s_par[wib][lane][6] = h_l;
    __syncwarp();

    // ---- Phase B: 2 grid cells per lane ----
    const float* ev = s_edge[wib];
    #pragma unroll
    for (int half = 0; half < 2; half++) {
        int g = lane + half * 32;
        float xg = (float)g * (1.0f / GCELLS);
        float xn = (float)(g + 1) * (1.0f / GCELLS);

        int b0 = (xg >= ev[16]) ? 16 : 0;
        b0 += (xg >= ev[b0 + 8]) ? 8 : 0;
        b0 += (xg >= ev[b0 + 4]) ? 4 : 0;
        b0 += (xg >= ev[b0 + 2]) ? 2 : 0;
        b0 += (xg >= ev[b0 + 1]) ? 1 : 0;

        bool single = (b0 >= KBINS - 1) || (ev[b0 + 1] >= xn);

        float4 ra, rb;
        if (single) {
            const float* p = s_par[wib][b0];
            ra = make_float4(__int_as_float(-1), p[0], p[1], p[2]);
            rb = make_float4(p[3], p[4], p[5], p[6]);
        } else {
            float ee[7];
            #pragma unroll
            for (int j = 0; j < 7; j++) {
                int idx = b0 + 1 + j;
                ee[j] = (idx < KBINS) ? ev[idx] : 2.0f;
            }
            ra = make_float4(__int_as_float(b0), ee[0], ee[1], ee[2]);
            rb = make_float4(ee[3], ee[4], ee[5], ee[6]);
        }
        stg256(&g_grid[(r * GCELLS + g) * 2], ra, rb);  // coalesced 32B/lane
    }
}

// ---------------------------------------------------------------------------
// Eval: FOUR points per thread.
//   P1: 4 grid records via LDG.256 (1 wavefront each, was 2)
//   P2: bin resolution (rare saturated walk)
//   P3: predicated params LDG.256, overwriting record regs -> unified params
//   P4: math + vector stores
// 32-bit offset arithmetic; bases hoisted (cuts 64-bit IMAD chains).
// ---------------------------------------------------------------------------
__global__ void __launch_bounds__(256, 4)
eval_points_kernel(const float4* __restrict__ x4,
                   const int4* __restrict__ ridx4,
                   float* __restrict__ out) {
    int t = blockIdx.x * blockDim.x + threadIdx.x;
    if (t >= NPTS / VEC) return;

    float4 xv = x4[t];
    int4   rv = ridx4[t];
    float xs[VEC] = {xv.x, xv.y, xv.z, xv.w};
    int   rs[VEC] = {rv.x, rv.y, rv.z, rv.w};

    const float4* __restrict__ gridbase = g_grid;
    const float4* __restrict__ parbase  = g_params;

    // P1: one 32B record load per point (32-bit offsets)
    float4 ra[VEC], rb[VEC];
    unsigned goff[VEC];
    #pragma unroll
    for (int k = 0; k < VEC; k++) {
        int g = min((int)(xs[k] * (float)GCELLS), GCELLS - 1);  // exact
        goff[k] = (unsigned)(rs[k] * (GCELLS * 2)) + (unsigned)(g * 2);
    }
    #pragma unroll
    for (int k = 0; k < VEC; k++) ldg256(gridbase + goff[k], ra[k], rb[k]);

    // P2: bin resolution
    bool multi[VEC];
    int  b[VEC];
    #pragma unroll
    for (int k = 0; k < VEC; k++) {
        float x = xs[k];
        multi[k] = (__float_as_int(ra[k].x) >= 0);
        int cnt = (x >= ra[k].y) + (x >= ra[k].z) + (x >= ra[k].w)
                + (x >= rb[k].x) + (x >= rb[k].y) + (x >= rb[k].z)
                + (x >= rb[k].w);
        b[k] = __float_as_int(ra[k].x) + cnt;
        if (multi[k] && cnt == 7) {  // saturated cell: exact fallback (~never)
            const float* e = g_edges + rs[k] * KBINS;
            while (b[k] < KBINS - 1 && x >= __ldg(e + b[k] + 1)) b[k]++;
        }
    }

    // P3: unify into ra/rb = {loc_l,inv_w,A,B}{cdf_l,dh,h_l,_}
    #pragma unroll
    for (int k = 0; k < VEC; k++) {
        if (multi[k]) {
            unsigned poff = (unsigned)(rs[k] * (KBINS * 2)) + (unsigned)(b[k] * 2);
            ldg256(parbase + poff, ra[k], rb[k]);
        } else {
            ra[k] = make_float4(ra[k].y, ra[k].z, ra[k].w, rb[k].x);
            rb[k] = make_float4(rb[k].y, rb[k].z, rb[k].w, 0.0f);
        }
    }

    // P4: epilogue
    float outv[VEC], lad[VEC];
    #pragma unroll
    for (int k = 0; k < VEC; k++) {
        float alpha = (xs[k] - ra[k].x) * ra[k].y;
        outv[k] = fmaf(fmaf(ra[k].z, alpha, ra[k].w), alpha, rb[k].x);
        lad[k]  = __logf(fmaf(rb[k].y, alpha, rb[k].z));
    }

    __stcs((float4*)(out) + t, make_float4(outv[0], outv[1], outv[2], outv[3]));
    __stcs((float4*)(out + NPTS) + t, make_float4(lad[0], lad[1], lad[2], lad[3]));
}

extern "C" void kernel_launch(void* const* d_in, const int* in_sizes, int n_in,
                              void* d_out, int out_size) {
    const float* x    = (const float*)d_in[0];
    const int*   ridx = (const int*)d_in[1];
    const float* uw   = (const float*)d_in[2];
    const float* uh   = (const float*)d_in[3];
    if (n_in >= 4 && in_sizes[2] == R_REGIONS * (KBINS + 1)
                  && in_sizes[3] == R_REGIONS * KBINS) {
        const float* tmp = uw; uw = uh; uh = tmp;
    }
    float* out = (float*)d_out;

    int blocks1 = (R_REGIONS + 7) / 8;
    build_kernel<<<blocks1, 256>>>(uw, uh);

    int threads2 = NPTS / VEC;
    int blocks2 = (threads2 + 255) / 256;
    eval_points_kernel<<<blocks2, 256>>>((const float4*)x, (const int4*)ridx, out);
}